// round 14
// baseline (speedup 1.0000x reference)
#include <cuda_runtime.h>
#include <cstdint>

// Problem constants (fixed by setup_inputs)
#define BB 4
#define CC 128
#define HH 96
#define WW 160
#define RR 4
#define SS 17   // 1 + 4*R

// Tiling: 32(w) x 16(h) tile, thread owns 2x2 pixels
#define TW 32
#define TH 16
#define BX 16
#define BY 8
#define NTHREADS (BX * BY)        // 128
#define HALO_W (TW + 2 * RR)      // 40
#define HALO_H (TH + 2 * RR)      // 24
#define HALO_N (HALO_H * HALO_W)  // 960 floats per channel
#define HALO_QW (HALO_W / 4)      // 10 quads per row
#define HALO_QN (HALO_N / 4)      // 240 quads per channel

#define NCHUNK 16
#define CPK (CC / NCHUNK)    // 8 channels per chunk
#define HW (HH * WW)

__device__ __forceinline__ void ffma2(uint64_t& acc, uint64_t a, uint64_t b) {
    asm("fma.rn.f32x2 %0, %1, %2, %0;" : "+l"(acc) : "l"(a), "l"(b));
}
__device__ __forceinline__ uint64_t pack2(float lo, float hi) {
    uint64_t r;
    asm("mov.b64 %0, {%1, %2};" : "=l"(r) : "f"(lo), "f"(hi));
    return r;
}
__device__ __forceinline__ void cp_async16(uint32_t saddr, const void* gaddr, int sz) {
    asm volatile("cp.async.ca.shared.global [%0], [%1], 16, %2;"
                 :: "r"(saddr), "l"(gaddr), "r"(sz) : "memory");
}
__device__ __forceinline__ void red_add_f2(float* p, uint64_t v) {
    float2 o;
    asm("mov.b64 {%0, %1}, %2;" : "=f"(o.x), "=f"(o.y) : "l"(v));
    atomicAdd((float2*)p, o);
}

__global__ __launch_bounds__(NTHREADS, 7)
void cost_volume_kernel(const float* __restrict__ src,
                        const float* __restrict__ tgt,
                        float* __restrict__ out) {
    __shared__ float sm[CPK * HALO_N];   // 8 * 960 * 4B = 30 KB

    const int tx = threadIdx.x;
    const int ty = threadIdx.y;
    const int tid = ty * BX + tx;
    const int w0 = blockIdx.x * TW;
    const int h0 = blockIdx.y * TH;
    const int b     = blockIdx.z >> 4;   // NCHUNK = 16
    const int chunk = blockIdx.z & 15;
    const int c0 = chunk * CPK;
    const int lx = 2 * tx;
    const int w  = w0 + lx;
    const int r0 = h0 + 2 * ty;          // first of this thread's two rows

    const float* tgtb  = tgt + ((long long)b * CC + c0) * HW;
    const float* srcp0 = src + (((long long)b * CC + c0) * HH + r0) * WW + w;

    // ---- single-shot staging: 240 quads/ch via cp.async.128 with zfill ----
    {
        int goff[2], szv[2];
#pragma unroll
        for (int k = 0; k < 2; k++) {
            int pos4 = tid + k * NTHREADS;   // quad index (k=1 valid for tid<112)
            int r    = pos4 / HALO_QW;
            int c4   = pos4 - r * HALO_QW;
            int gr   = h0 - RR + r;
            int gc   = w0 - RR + 4 * c4;     // 16B aligned; quad fully in or out
            bool ok  = ((unsigned)gr < (unsigned)HH) & ((unsigned)gc < (unsigned)WW);
            goff[k] = gr * WW + gc;
            szv[k]  = ok ? 16 : 0;
        }
        const uint32_t sbase = (uint32_t)__cvta_generic_to_shared(sm);
        const bool k1on = tid < HALO_QN - NTHREADS;   // tid < 112
#pragma unroll
        for (int ch = 0; ch < CPK; ch++) {
            const float* tc = tgtb + ch * HW;
            const uint32_t sc = sbase + ch * (HALO_N * 4);
            cp_async16(sc + tid * 16, tc + goff[0], szv[0]);
            if (k1on)
                cp_async16(sc + (tid + NTHREADS) * 16, tc + goff[1], szv[1]);
        }
        asm volatile("cp.async.commit_group;" ::: "memory");
        asm volatile("cp.async.wait_group 0;" ::: "memory");
    }
    __syncthreads();

    const int hr = 2 * ty + RR;               // halo row of r0
    const int hbase = hr * HALO_W + lx;       // horizontal span base, row r0
    float* ob = out + (((long long)b * SS) * HH + r0) * WW + w;

    // ================= PASS H: 9 horizontal shifts x 2 rows =================
    {
        uint64_t aH0[9], aH1[9];
#pragma unroll
        for (int k = 0; k < 9; k++) { aH0[k] = 0ull; aH1[k] = 0ull; }

#pragma unroll
        for (int ch = 0; ch < CPK; ch++) {
            const uint64_t sv0 = *(const uint64_t*)(srcp0 + ch * HW);
            const uint64_t sv1 = *(const uint64_t*)(srcp0 + ch * HW + WW);
            const float* smc = sm + ch * HALO_N;

            // row r0
            {
                float2 t0 = *(const float2*)(smc + hbase + 0);
                float2 t1 = *(const float2*)(smc + hbase + 2);
                float2 t2 = *(const float2*)(smc + hbase + 4);
                float2 t3 = *(const float2*)(smc + hbase + 6);
                float2 t4 = *(const float2*)(smc + hbase + 8);
                ffma2(aH0[0], sv0, pack2(t2.x, t2.y));   // s=0
                ffma2(aH0[1], sv0, pack2(t1.y, t2.x));   // s=3
                ffma2(aH0[2], sv0, pack2(t2.y, t3.x));   // s=4
                ffma2(aH0[3], sv0, pack2(t1.x, t1.y));   // s=7
                ffma2(aH0[4], sv0, pack2(t3.x, t3.y));   // s=8
                ffma2(aH0[5], sv0, pack2(t0.y, t1.x));   // s=11
                ffma2(aH0[6], sv0, pack2(t3.y, t4.x));   // s=12
                ffma2(aH0[7], sv0, pack2(t0.x, t0.y));   // s=15
                ffma2(aH0[8], sv0, pack2(t4.x, t4.y));   // s=16
            }
            // row r1
            {
                const int hb1 = hbase + HALO_W;
                float2 t0 = *(const float2*)(smc + hb1 + 0);
                float2 t1 = *(const float2*)(smc + hb1 + 2);
                float2 t2 = *(const float2*)(smc + hb1 + 4);
                float2 t3 = *(const float2*)(smc + hb1 + 6);
                float2 t4 = *(const float2*)(smc + hb1 + 8);
                ffma2(aH1[0], sv1, pack2(t2.x, t2.y));
                ffma2(aH1[1], sv1, pack2(t1.y, t2.x));
                ffma2(aH1[2], sv1, pack2(t2.y, t3.x));
                ffma2(aH1[3], sv1, pack2(t1.x, t1.y));
                ffma2(aH1[4], sv1, pack2(t3.x, t3.y));
                ffma2(aH1[5], sv1, pack2(t0.y, t1.x));
                ffma2(aH1[6], sv1, pack2(t3.y, t4.x));
                ffma2(aH1[7], sv1, pack2(t0.x, t0.y));
                ffma2(aH1[8], sv1, pack2(t4.x, t4.y));
            }
        }
        const int smap[9] = {0, 3, 4, 7, 8, 11, 12, 15, 16};
#pragma unroll
        for (int k = 0; k < 9; k++) {
            red_add_f2(ob + smap[k] * HW,      aH0[k]);
            red_add_f2(ob + smap[k] * HW + WW, aH1[k]);
        }
    }

    // ================= PASS V: 8 vertical shifts x 2 rows ===================
    {
        uint64_t aV0[8], aV1[8];
#pragma unroll
        for (int k = 0; k < 8; k++) { aV0[k] = 0ull; aV1[k] = 0ull; }

        const int vb = lx + RR;   // center column
#pragma unroll
        for (int ch = 0; ch < CPK; ch++) {
            const uint64_t sv0 = *(const uint64_t*)(srcp0 + ch * HW);
            const uint64_t sv1 = *(const uint64_t*)(srcp0 + ch * HW + WW);
            const float* vc = sm + ch * HALO_N + vb;

            // shared vertical column: rows hr-4 .. hr+5 (10 pairs, both rows)
            uint64_t v[10];
#pragma unroll
            for (int j = 0; j < 10; j++)
                v[j] = *(const uint64_t*)(vc + (hr - 4 + j) * HALO_W);

#pragma unroll
            for (int i2 = 1; i2 <= RR; i2++) {
                ffma2(aV0[2 * i2 - 2], sv0, v[4 - i2]);   // r0 up   s=4i-3
                ffma2(aV0[2 * i2 - 1], sv0, v[4 + i2]);   // r0 down s=4i-2
                ffma2(aV1[2 * i2 - 2], sv1, v[5 - i2]);   // r1 up
                ffma2(aV1[2 * i2 - 1], sv1, v[5 + i2]);   // r1 down
            }
        }
#pragma unroll
        for (int i2 = 1; i2 <= RR; i2++) {
            red_add_f2(ob + (4 * i2 - 3) * HW,      aV0[2 * i2 - 2]);
            red_add_f2(ob + (4 * i2 - 2) * HW,      aV0[2 * i2 - 1]);
            red_add_f2(ob + (4 * i2 - 3) * HW + WW, aV1[2 * i2 - 2]);
            red_add_f2(ob + (4 * i2 - 2) * HW + WW, aV1[2 * i2 - 1]);
        }
    }
}

extern "C" void kernel_launch(void* const* d_in, const int* in_sizes, int n_in,
                              void* d_out, int out_size) {
    const float* src = (const float*)d_in[0];
    const float* tgt = (const float*)d_in[1];
    float* out = (float*)d_out;

    cudaMemsetAsync(out, 0, (size_t)out_size * sizeof(float), 0);

    dim3 block(BX, BY);
    dim3 grid(WW / TW, HH / TH, BB * NCHUNK);   // 5 x 6 x 64 = 1920 CTAs
    cost_volume_kernel<<<grid, block>>>(src, tgt, out);
}

// round 15
// speedup vs baseline: 1.6877x; 1.6877x over previous
#include <cuda_runtime.h>
#include <cstdint>

// Problem constants (fixed by setup_inputs)
#define BB 4
#define CC 128
#define HH 96
#define WW 160
#define RR 4
#define SS 17   // 1 + 4*R

#define BX 16
#define BY 8
#define NTHREADS (BX * BY)   // 128
#define HW (HH * WW)

#define NCH 4                // channel chunks
#define CPK (CC / NCH)       // 32 channels per chunk
#define STAGE_CH 4
#define NSTAGE (CPK / STAGE_CH)  // 8 stages

// ---- H-CTA geometry: tile 32x8, halo 40x8 (w-halo only) ----
#define H_TW 32
#define H_TH 8
#define H_HALO_W 40
#define H_HALO_N (H_HALO_W * H_TH)     // 320 floats
#define H_QN (H_HALO_N / 4)            // 80 quads
#define H_QW (H_HALO_W / 4)            // 10 quads/row
#define H_YT (HH / H_TH)               // 12 h-tiles

// ---- V-CTA geometry: tile 32x16, halo 32x24 (h-halo only) ----
#define V_TW 32
#define V_TH 16
#define V_HALO_W 32
#define V_HALO_H (V_TH + 2 * RR)       // 24
#define V_HALO_N (V_HALO_W * V_HALO_H) // 768 floats
#define V_QN (V_HALO_N / 4)            // 192 quads
#define V_QW (V_HALO_W / 4)            // 8 quads/row
#define V_YT (HH / V_TH)               // 6 v-tiles

#define BUF_FLOATS (STAGE_CH * V_HALO_N)   // 3072 floats (max of both paths)

__device__ __forceinline__ void ffma2(uint64_t& acc, uint64_t a, uint64_t b) {
    asm("fma.rn.f32x2 %0, %1, %2, %0;" : "+l"(acc) : "l"(a), "l"(b));
}
__device__ __forceinline__ uint64_t pack2(float lo, float hi) {
    uint64_t r;
    asm("mov.b64 %0, {%1, %2};" : "=l"(r) : "f"(lo), "f"(hi));
    return r;
}
__device__ __forceinline__ void cp_async16(uint32_t saddr, const void* gaddr, int sz) {
    asm volatile("cp.async.ca.shared.global [%0], [%1], 16, %2;"
                 :: "r"(saddr), "l"(gaddr), "r"(sz) : "memory");
}
__device__ __forceinline__ void red_add_f2(float* p, uint64_t v) {
    float2 o;
    asm("mov.b64 {%0, %1}, %2;" : "=f"(o.x), "=f"(o.y) : "l"(v));
    atomicAdd((float2*)p, o);
}

__global__ __launch_bounds__(NTHREADS, 8)
void cost_volume_kernel(const float* __restrict__ src,
                        const float* __restrict__ tgt,
                        float* __restrict__ out) {
    __shared__ float sm[2 * BUF_FLOATS];   // 24 KB double buffer

    const int tx = threadIdx.x;
    const int ty = threadIdx.y;
    const int tid = ty * BX + tx;
    const int w0 = blockIdx.x * 32;
    const int b     = blockIdx.z >> 2;     // NCH = 4
    const int chunk = blockIdx.z & 3;
    const int c0 = chunk * CPK;
    const int lx = 2 * tx;
    const int w  = w0 + lx;

    const float* tgtb = tgt + ((long long)b * CC + c0) * HW;
    const uint32_t sbase = (uint32_t)__cvta_generic_to_shared(sm);

    if (blockIdx.y < H_YT) {
        // ===================== H-CTA: 9 horizontal shifts =====================
        const int h0 = blockIdx.y * H_TH;
        const int h  = h0 + ty;
        const float* srcp = src + (((long long)b * CC + c0) * HH + h) * WW + w;

        // staging offsets: 80 quads/ch, thread tid<80 stages one quad per ch
        int goff = 0, szv = 0;
        if (tid < H_QN) {
            int r  = tid / H_QW;
            int c4 = tid - r * H_QW;
            int gc = w0 - RR + 4 * c4;        // may be out in w; rows always valid
            bool ok = (unsigned)gc < (unsigned)WW;
            goff = (h0 + r) * WW + gc;
            szv  = ok ? 16 : 0;
        }
        auto stage_load = [&](int st) {
            const uint32_t sb = sbase + (st & 1) * (BUF_FLOATS * 4);
            const float* tb = tgtb + st * STAGE_CH * HW;
            if (tid < H_QN) {
#pragma unroll
                for (int ch = 0; ch < STAGE_CH; ch++)
                    cp_async16(sb + ch * (H_HALO_N * 4) + tid * 16, tb + ch * HW + goff, szv);
            }
            asm volatile("cp.async.commit_group;" ::: "memory");
        };

        stage_load(0);
        uint64_t acc[9];
#pragma unroll
        for (int k = 0; k < 9; k++) acc[k] = 0ull;

        const int rowbase = ty * H_HALO_W + lx;
        uint64_t sv_cur = *(const uint64_t*)(srcp);

#pragma unroll 1
        for (int st = 0; st < NSTAGE; st++) {
            if (st + 1 < NSTAGE) {
                stage_load(st + 1);
                asm volatile("cp.async.wait_group 1;" ::: "memory");
            } else {
                asm volatile("cp.async.wait_group 0;" ::: "memory");
            }
            __syncthreads();
            const float* smb = sm + (st & 1) * BUF_FLOATS;
#pragma unroll
            for (int ch = 0; ch < STAGE_CH; ch++) {
                const int gch = st * STAGE_CH + ch;
                uint64_t sv_nxt = 0ull;
                if (gch + 1 < CPK)
                    sv_nxt = *(const uint64_t*)(srcp + (gch + 1) * HW);

                const float* smc = smb + ch * H_HALO_N;
                float2 t0 = *(const float2*)(smc + rowbase + 0);
                float2 t1 = *(const float2*)(smc + rowbase + 2);
                float2 t2 = *(const float2*)(smc + rowbase + 4);
                float2 t3 = *(const float2*)(smc + rowbase + 6);
                float2 t4 = *(const float2*)(smc + rowbase + 8);

                ffma2(acc[0], sv_cur, pack2(t2.x, t2.y));   // s=0
                ffma2(acc[1], sv_cur, pack2(t1.y, t2.x));   // s=3
                ffma2(acc[2], sv_cur, pack2(t2.y, t3.x));   // s=4
                ffma2(acc[3], sv_cur, pack2(t1.x, t1.y));   // s=7
                ffma2(acc[4], sv_cur, pack2(t3.x, t3.y));   // s=8
                ffma2(acc[5], sv_cur, pack2(t0.y, t1.x));   // s=11
                ffma2(acc[6], sv_cur, pack2(t3.y, t4.x));   // s=12
                ffma2(acc[7], sv_cur, pack2(t0.x, t0.y));   // s=15
                ffma2(acc[8], sv_cur, pack2(t4.x, t4.y));   // s=16
                sv_cur = sv_nxt;
            }
            __syncthreads();
        }

        float* ob = out + (((long long)b * SS) * HH + h) * WW + w;
        const int smap[9] = {0, 3, 4, 7, 8, 11, 12, 15, 16};
#pragma unroll
        for (int k = 0; k < 9; k++)
            red_add_f2(ob + smap[k] * HW, acc[k]);

    } else {
        // ===================== V-CTA: 8 vertical shifts, 2 rows/thread =======
        const int h0 = (blockIdx.y - H_YT) * V_TH;
        const int r0 = h0 + 2 * ty;
        const float* srcp0 = src + (((long long)b * CC + c0) * HH + r0) * WW + w;

        // staging: 192 quads/ch -> slot0 all threads, slot1 tid<64
        int goff[2], szv[2];
#pragma unroll
        for (int k = 0; k < 2; k++) {
            int q  = tid + k * NTHREADS;
            int r  = q / V_QW;
            int c4 = q - r * V_QW;
            int gr = h0 - RR + r;               // may be out in h; cols always valid
            bool ok = (unsigned)gr < (unsigned)HH;
            goff[k] = gr * WW + w0 + 4 * c4;
            szv[k]  = ok ? 16 : 0;
        }
        const bool k1on = tid < V_QN - NTHREADS;   // tid < 64
        auto stage_load = [&](int st) {
            const uint32_t sb = sbase + (st & 1) * (BUF_FLOATS * 4);
            const float* tb = tgtb + st * STAGE_CH * HW;
#pragma unroll
            for (int ch = 0; ch < STAGE_CH; ch++) {
                const uint32_t sc = sb + ch * (V_HALO_N * 4);
                cp_async16(sc + tid * 16, tb + ch * HW + goff[0], szv[0]);
                if (k1on)
                    cp_async16(sc + (tid + NTHREADS) * 16, tb + ch * HW + goff[1], szv[1]);
            }
            asm volatile("cp.async.commit_group;" ::: "memory");
        };

        stage_load(0);
        uint64_t aV0[8], aV1[8];
#pragma unroll
        for (int k = 0; k < 8; k++) { aV0[k] = 0ull; aV1[k] = 0ull; }

#pragma unroll 1
        for (int st = 0; st < NSTAGE; st++) {
            if (st + 1 < NSTAGE) {
                stage_load(st + 1);
                asm volatile("cp.async.wait_group 1;" ::: "memory");
            } else {
                asm volatile("cp.async.wait_group 0;" ::: "memory");
            }
            __syncthreads();
            const float* smb = sm + (st & 1) * BUF_FLOATS;
#pragma unroll
            for (int ch = 0; ch < STAGE_CH; ch++) {
                const int gch = st * STAGE_CH + ch;
                const uint64_t sv0 = *(const uint64_t*)(srcp0 + gch * HW);
                const uint64_t sv1 = *(const uint64_t*)(srcp0 + gch * HW + WW);

                // shared column pairs: local rows 2ty .. 2ty+9 (= global r0-4 .. r0+5)
                const float* vc = smb + ch * V_HALO_N + lx;
                uint64_t v[10];
#pragma unroll
                for (int j = 0; j < 10; j++)
                    v[j] = *(const uint64_t*)(vc + (2 * ty + j) * V_HALO_W);

#pragma unroll
                for (int i2 = 1; i2 <= RR; i2++) {
                    ffma2(aV0[2 * i2 - 2], sv0, v[4 - i2]);   // r0 up   s=4i-3
                    ffma2(aV0[2 * i2 - 1], sv0, v[4 + i2]);   // r0 down s=4i-2
                    ffma2(aV1[2 * i2 - 2], sv1, v[5 - i2]);   // r1 up
                    ffma2(aV1[2 * i2 - 1], sv1, v[5 + i2]);   // r1 down
                }
            }
            __syncthreads();
        }

        float* ob = out + (((long long)b * SS) * HH + r0) * WW + w;
#pragma unroll
        for (int i2 = 1; i2 <= RR; i2++) {
            red_add_f2(ob + (4 * i2 - 3) * HW,      aV0[2 * i2 - 2]);
            red_add_f2(ob + (4 * i2 - 2) * HW,      aV0[2 * i2 - 1]);
            red_add_f2(ob + (4 * i2 - 3) * HW + WW, aV1[2 * i2 - 2]);
            red_add_f2(ob + (4 * i2 - 2) * HW + WW, aV1[2 * i2 - 1]);
        }
    }
}

extern "C" void kernel_launch(void* const* d_in, const int* in_sizes, int n_in,
                              void* d_out, int out_size) {
    const float* src = (const float*)d_in[0];
    const float* tgt = (const float*)d_in[1];
    float* out = (float*)d_out;

    cudaMemsetAsync(out, 0, (size_t)out_size * sizeof(float), 0);

    dim3 block(BX, BY);
    dim3 grid(WW / 32, H_YT + V_YT, BB * NCH);   // 5 x 18 x 16 = 1440 CTAs
    cost_volume_kernel<<<grid, block>>>(src, tgt, out);
}

// round 16
// speedup vs baseline: 1.7176x; 1.0177x over previous
#include <cuda_runtime.h>
#include <cstdint>

// Problem constants (fixed by setup_inputs)
#define BB 4
#define CC 128
#define HH 96
#define WW 160
#define RR 4
#define SS 17   // 1 + 4*R

#define BX 16
#define BY 8
#define NTHREADS (BX * BY)   // 128
#define HW (HH * WW)

#define NCH 4                // channel chunks
#define CPK (CC / NCH)       // 32 channels per chunk
#define STAGE_CH 4
#define NSTAGE (CPK / STAGE_CH)  // 8 stages

// ---- H-CTA geometry: tile 32x8, halo 40x8 (w-halo only) ----
#define H_TH 8
#define H_HALO_W 40
#define H_HALO_N (H_HALO_W * H_TH)     // 320 floats
#define H_QN (H_HALO_N / 4)            // 80 quads
#define H_QW (H_HALO_W / 4)            // 10 quads/row
#define H_YT (HH / H_TH)               // 12 h-tiles

// ---- V-CTA geometry: tile 32x16, halo 32x24 (h-halo only) ----
#define V_TH 16
#define V_HALO_W 32
#define V_HALO_H (V_TH + 2 * RR)       // 24
#define V_HALO_N (V_HALO_W * V_HALO_H) // 768 floats
#define V_QN (V_HALO_N / 4)            // 192 quads
#define V_QW (V_HALO_W / 4)            // 8 quads/row
#define V_YT (HH / V_TH)               // 6 v-tiles

#define BUF_FLOATS (STAGE_CH * V_HALO_N)   // 3072 floats (max of both paths)

__device__ __forceinline__ void ffma2(uint64_t& acc, uint64_t a, uint64_t b) {
    asm("fma.rn.f32x2 %0, %1, %2, %0;" : "+l"(acc) : "l"(a), "l"(b));
}
__device__ __forceinline__ uint64_t pack2(float lo, float hi) {
    uint64_t r;
    asm("mov.b64 %0, {%1, %2};" : "=l"(r) : "f"(lo), "f"(hi));
    return r;
}
__device__ __forceinline__ void cp_async16(uint32_t saddr, const void* gaddr, int sz) {
    asm volatile("cp.async.ca.shared.global [%0], [%1], 16, %2;"
                 :: "r"(saddr), "l"(gaddr), "r"(sz) : "memory");
}
__device__ __forceinline__ void red_add_f2(float* p, uint64_t v) {
    float2 o;
    asm("mov.b64 {%0, %1}, %2;" : "=f"(o.x), "=f"(o.y) : "l"(v));
    atomicAdd((float2*)p, o);
}

__global__ __launch_bounds__(NTHREADS, 8)
void cost_volume_kernel(const float* __restrict__ src,
                        const float* __restrict__ tgt,
                        float* __restrict__ out) {
    __shared__ float sm[2 * BUF_FLOATS];   // 24 KB double buffer

    const int tx = threadIdx.x;
    const int ty = threadIdx.y;
    const int tid = ty * BX + tx;
    const int w0 = blockIdx.x * 32;
    const int b     = blockIdx.z >> 2;     // NCH = 4
    const int chunk = blockIdx.z & 3;
    const int c0 = chunk * CPK;
    const int lx = 2 * tx;
    const int w  = w0 + lx;

    const float* tgtb = tgt + ((long long)b * CC + c0) * HW;
    const uint32_t sbase = (uint32_t)__cvta_generic_to_shared(sm);

    if (blockIdx.y < V_YT) {
        // ===================== V-CTA: 8 vertical shifts, 2 rows/thread =======
        const int h0 = blockIdx.y * V_TH;
        const int r0 = h0 + 2 * ty;
        const float* srcp0 = src + (((long long)b * CC + c0) * HH + r0) * WW + w;

        // staging: 192 quads/ch -> slot0 all threads, slot1 tid<64
        int goff[2], szv[2];
#pragma unroll
        for (int k = 0; k < 2; k++) {
            int q  = tid + k * NTHREADS;
            int r  = q / V_QW;
            int c4 = q - r * V_QW;
            int gr = h0 - RR + r;               // may be out in h; cols always valid
            bool ok = (unsigned)gr < (unsigned)HH;
            goff[k] = gr * WW + w0 + 4 * c4;
            szv[k]  = ok ? 16 : 0;
        }
        const bool k1on = tid < V_QN - NTHREADS;   // tid < 64
        auto stage_load = [&](int st) {
            const uint32_t sb = sbase + (st & 1) * (BUF_FLOATS * 4);
            const float* tb = tgtb + st * STAGE_CH * HW;
#pragma unroll
            for (int ch = 0; ch < STAGE_CH; ch++) {
                const uint32_t sc = sb + ch * (V_HALO_N * 4);
                cp_async16(sc + tid * 16, tb + ch * HW + goff[0], szv[0]);
                if (k1on)
                    cp_async16(sc + (tid + NTHREADS) * 16, tb + ch * HW + goff[1], szv[1]);
            }
            asm volatile("cp.async.commit_group;" ::: "memory");
        };

        stage_load(0);
        uint64_t aV0[8], aV1[8];
#pragma unroll
        for (int k = 0; k < 8; k++) { aV0[k] = 0ull; aV1[k] = 0ull; }

        // 1-deep src prefetch for both rows
        uint64_t sv0_cur = *(const uint64_t*)(srcp0);
        uint64_t sv1_cur = *(const uint64_t*)(srcp0 + WW);

#pragma unroll 1
        for (int st = 0; st < NSTAGE; st++) {
            if (st + 1 < NSTAGE) {
                stage_load(st + 1);
                asm volatile("cp.async.wait_group 1;" ::: "memory");
            } else {
                asm volatile("cp.async.wait_group 0;" ::: "memory");
            }
            __syncthreads();
            const float* smb = sm + (st & 1) * BUF_FLOATS;
#pragma unroll
            for (int ch = 0; ch < STAGE_CH; ch++) {
                const int gch = st * STAGE_CH + ch;
                uint64_t sv0_nxt = 0ull, sv1_nxt = 0ull;
                if (gch + 1 < CPK) {
                    sv0_nxt = *(const uint64_t*)(srcp0 + (gch + 1) * HW);
                    sv1_nxt = *(const uint64_t*)(srcp0 + (gch + 1) * HW + WW);
                }

                // shared column pairs: local rows 2ty .. 2ty+9 (= global r0-4 .. r0+5)
                const float* vc = smb + ch * V_HALO_N + lx;
#pragma unroll
                for (int i2 = 1; i2 <= RR; i2++) {
                    uint64_t vu0 = *(const uint64_t*)(vc + (2 * ty + 4 - i2) * V_HALO_W);
                    uint64_t vd0 = *(const uint64_t*)(vc + (2 * ty + 4 + i2) * V_HALO_W);
                    uint64_t vu1 = *(const uint64_t*)(vc + (2 * ty + 5 - i2) * V_HALO_W);
                    uint64_t vd1 = *(const uint64_t*)(vc + (2 * ty + 5 + i2) * V_HALO_W);
                    ffma2(aV0[2 * i2 - 2], sv0_cur, vu0);   // r0 up   s=4i-3
                    ffma2(aV0[2 * i2 - 1], sv0_cur, vd0);   // r0 down s=4i-2
                    ffma2(aV1[2 * i2 - 2], sv1_cur, vu1);   // r1 up
                    ffma2(aV1[2 * i2 - 1], sv1_cur, vd1);   // r1 down
                }
                sv0_cur = sv0_nxt;
                sv1_cur = sv1_nxt;
            }
            __syncthreads();
        }

        float* ob = out + (((long long)b * SS) * HH + r0) * WW + w;
#pragma unroll
        for (int i2 = 1; i2 <= RR; i2++) {
            red_add_f2(ob + (4 * i2 - 3) * HW,      aV0[2 * i2 - 2]);
            red_add_f2(ob + (4 * i2 - 2) * HW,      aV0[2 * i2 - 1]);
            red_add_f2(ob + (4 * i2 - 3) * HW + WW, aV1[2 * i2 - 2]);
            red_add_f2(ob + (4 * i2 - 2) * HW + WW, aV1[2 * i2 - 1]);
        }

    } else {
        // ===================== H-CTA: 9 horizontal shifts =====================
        const int h0 = (blockIdx.y - V_YT) * H_TH;
        const int h  = h0 + ty;
        const float* srcp = src + (((long long)b * CC + c0) * HH + h) * WW + w;

        // staging offsets: 80 quads/ch, thread tid<80 stages one quad per ch
        int goff = 0, szv = 0;
        if (tid < H_QN) {
            int r  = tid / H_QW;
            int c4 = tid - r * H_QW;
            int gc = w0 - RR + 4 * c4;        // may be out in w; rows always valid
            bool ok = (unsigned)gc < (unsigned)WW;
            goff = (h0 + r) * WW + gc;
            szv  = ok ? 16 : 0;
        }
        auto stage_load = [&](int st) {
            const uint32_t sb = sbase + (st & 1) * (BUF_FLOATS * 4);
            const float* tb = tgtb + st * STAGE_CH * HW;
            if (tid < H_QN) {
#pragma unroll
                for (int ch = 0; ch < STAGE_CH; ch++)
                    cp_async16(sb + ch * (H_HALO_N * 4) + tid * 16, tb + ch * HW + goff, szv);
            }
            asm volatile("cp.async.commit_group;" ::: "memory");
        };

        stage_load(0);
        uint64_t acc[9];
#pragma unroll
        for (int k = 0; k < 9; k++) acc[k] = 0ull;

        const int rowbase = ty * H_HALO_W + lx;
        uint64_t sv_cur = *(const uint64_t*)(srcp);

#pragma unroll 1
        for (int st = 0; st < NSTAGE; st++) {
            if (st + 1 < NSTAGE) {
                stage_load(st + 1);
                asm volatile("cp.async.wait_group 1;" ::: "memory");
            } else {
                asm volatile("cp.async.wait_group 0;" ::: "memory");
            }
            __syncthreads();
            const float* smb = sm + (st & 1) * BUF_FLOATS;
#pragma unroll
            for (int ch = 0; ch < STAGE_CH; ch++) {
                const int gch = st * STAGE_CH + ch;
                uint64_t sv_nxt = 0ull;
                if (gch + 1 < CPK)
                    sv_nxt = *(const uint64_t*)(srcp + (gch + 1) * HW);

                const float* smc = smb + ch * H_HALO_N;
                float2 t0 = *(const float2*)(smc + rowbase + 0);
                float2 t1 = *(const float2*)(smc + rowbase + 2);
                float2 t2 = *(const float2*)(smc + rowbase + 4);
                float2 t3 = *(const float2*)(smc + rowbase + 6);
                float2 t4 = *(const float2*)(smc + rowbase + 8);

                ffma2(acc[0], sv_cur, pack2(t2.x, t2.y));   // s=0
                ffma2(acc[1], sv_cur, pack2(t1.y, t2.x));   // s=3
                ffma2(acc[2], sv_cur, pack2(t2.y, t3.x));   // s=4
                ffma2(acc[3], sv_cur, pack2(t1.x, t1.y));   // s=7
                ffma2(acc[4], sv_cur, pack2(t3.x, t3.y));   // s=8
                ffma2(acc[5], sv_cur, pack2(t0.y, t1.x));   // s=11
                ffma2(acc[6], sv_cur, pack2(t3.y, t4.x));   // s=12
                ffma2(acc[7], sv_cur, pack2(t0.x, t0.y));   // s=15
                ffma2(acc[8], sv_cur, pack2(t4.x, t4.y));   // s=16
                sv_cur = sv_nxt;
            }
            __syncthreads();
        }

        float* ob = out + (((long long)b * SS) * HH + h) * WW + w;
        const int smap[9] = {0, 3, 4, 7, 8, 11, 12, 15, 16};
#pragma unroll
        for (int k = 0; k < 9; k++)
            red_add_f2(ob + smap[k] * HW, acc[k]);
    }
}

extern "C" void kernel_launch(void* const* d_in, const int* in_sizes, int n_in,
                              void* d_out, int out_size) {
    const float* src = (const float*)d_in[0];
    const float* tgt = (const float*)d_in[1];
    float* out = (float*)d_out;

    cudaMemsetAsync(out, 0, (size_t)out_size * sizeof(float), 0);

    dim3 block(BX, BY);
    dim3 grid(WW / 32, V_YT + H_YT, BB * NCH);   // 5 x 18 x 16 = 1440 CTAs
    cost_volume_kernel<<<grid, block>>>(src, tgt, out);
}